// round 1
// baseline (speedup 1.0000x reference)
#include <cuda_runtime.h>

// Problem constants (fixed by the reference: B=4, H=W=256, C=192, WS=8, NH=6)
#define M_TOK   262144      // B * H * W
#define C_DIM   192
#define NHEAD   6
#define HD      32
#define NWIN    4096        // 4 * 32 * 32 windows
#define QKV_N   576         // 3 * C

// Scratch (allocation-free rule: __device__ globals)
__device__ float g_qkv[(size_t)M_TOK * QKV_N];   // ~604 MB
__device__ float g_att[(size_t)M_TOK * C_DIM];   // ~201 MB

// ---------------------------------------------------------------------------
// GEMM: C[M,N] = A[M,K] @ W[N,K]^T + bias[N]   (both inputs K-contiguous)
// 64x64 block tile, BK=16, 256 threads, 4x4 register micro-tile.
// ---------------------------------------------------------------------------
__global__ void __launch_bounds__(256) gemm_nt_kernel(
    const float* __restrict__ A, const float* __restrict__ W,
    const float* __restrict__ bias, float* __restrict__ C,
    int M, int N, int K)
{
    __shared__ float As[16][68];   // [k][m], stride 68 -> 16B-aligned float4 rows, reduced conflicts
    __shared__ float Bs[16][68];   // [k][n]

    const int bm = blockIdx.x * 64;
    const int bn = blockIdx.y * 64;
    const int t  = threadIdx.x;
    const int tx = t & 15;
    const int ty = t >> 4;
    const int lr = t >> 2;          // 0..63 : row within tile
    const int lc = (t & 3) << 2;    // 0,4,8,12 : k-offset within BK

    const float* Ag = A + (size_t)(bm + lr) * K + lc;
    const float* Wg = W + (size_t)(bn + lr) * K + lc;

    float acc[4][4] = {};

    for (int k0 = 0; k0 < K; k0 += 16) {
        float4 a = *(const float4*)(Ag + k0);
        float4 b = *(const float4*)(Wg + k0);
        __syncthreads();
        As[lc + 0][lr] = a.x; As[lc + 1][lr] = a.y;
        As[lc + 2][lr] = a.z; As[lc + 3][lr] = a.w;
        Bs[lc + 0][lr] = b.x; Bs[lc + 1][lr] = b.y;
        Bs[lc + 2][lr] = b.z; Bs[lc + 3][lr] = b.w;
        __syncthreads();
        #pragma unroll
        for (int k = 0; k < 16; ++k) {
            float4 av = *(const float4*)(&As[k][ty * 4]);
            float4 bv = *(const float4*)(&Bs[k][tx * 4]);
            float af[4] = {av.x, av.y, av.z, av.w};
            float bf[4] = {bv.x, bv.y, bv.z, bv.w};
            #pragma unroll
            for (int i = 0; i < 4; ++i)
                #pragma unroll
                for (int j = 0; j < 4; ++j)
                    acc[i][j] = fmaf(af[i], bf[j], acc[i][j]);
        }
    }

    float4 bb = *(const float4*)(bias + bn + tx * 4);
    #pragma unroll
    for (int i = 0; i < 4; ++i) {
        float4 o;
        o.x = acc[i][0] + bb.x;
        o.y = acc[i][1] + bb.y;
        o.z = acc[i][2] + bb.z;
        o.w = acc[i][3] + bb.w;
        *(float4*)(C + (size_t)(bm + ty * 4 + i) * N + bn + tx * 4) = o;
    }
}

// ---------------------------------------------------------------------------
// Window attention: one block per (window, head).
// qkv layout per token: [3][NH][HD] (n = which*192 + h*32 + d)
// S = (Q*scale) K^T + bias ; softmax rows ; O = P V ; write token-major.
// ---------------------------------------------------------------------------
__global__ void __launch_bounds__(256) attn_kernel(
    const float* __restrict__ qkv, const float* __restrict__ bias,
    float* __restrict__ out)
{
    __shared__ float Qs[32][68];   // [d][p]
    __shared__ float Ks[32][68];   // [d][p]
    __shared__ float Vs[64][32];   // [p][d]
    __shared__ float Ps[64][68];   // [j][i]  (P transposed)

    const int w  = blockIdx.x;
    const int h  = blockIdx.y;
    const int b  = w >> 10;
    const int wi = w & 1023;
    const int wh = wi >> 5;
    const int ww = wi & 31;
    const int t  = threadIdx.x;

    const float scale = 0.17677669529663687f;   // 1/sqrt(32)

    // ---- load Q (pre-scaled), K, V ----
    #pragma unroll
    for (int it = 0; it < 2; ++it) {
        int idx = t + it * 256;          // 0..511
        int p = idx >> 3;                // token in window 0..63
        int c = idx & 7;                 // float4 chunk 0..7 (32 dims)
        int r  = wh * 8 + (p >> 3);
        int cc = ww * 8 + (p & 7);
        size_t tok = (size_t)((b << 16) + r * 256 + cc);
        const float* base = qkv + tok * QKV_N + h * HD + c * 4;
        float4 q4 = *(const float4*)(base);
        float4 k4 = *(const float4*)(base + 192);
        float4 v4 = *(const float4*)(base + 384);
        int d = c * 4;
        Qs[d + 0][p] = q4.x * scale; Qs[d + 1][p] = q4.y * scale;
        Qs[d + 2][p] = q4.z * scale; Qs[d + 3][p] = q4.w * scale;
        Ks[d + 0][p] = k4.x; Ks[d + 1][p] = k4.y;
        Ks[d + 2][p] = k4.z; Ks[d + 3][p] = k4.w;
        *(float4*)(&Vs[p][d]) = v4;
    }
    __syncthreads();

    // ---- S = Q K^T : 4x4 micro-tile per thread ----
    const int tx = t & 15;   // key group
    const int ty = t >> 4;   // query group
    float acc[4][4] = {};
    #pragma unroll
    for (int d = 0; d < 32; ++d) {
        float4 av = *(const float4*)(&Qs[d][ty * 4]);
        float4 bv = *(const float4*)(&Ks[d][tx * 4]);
        float af[4] = {av.x, av.y, av.z, av.w};
        float bf[4] = {bv.x, bv.y, bv.z, bv.w};
        #pragma unroll
        for (int i = 0; i < 4; ++i)
            #pragma unroll
            for (int j = 0; j < 4; ++j)
                acc[i][j] = fmaf(af[i], bf[j], acc[i][j]);
    }

    // ---- bias + softmax (row lives in 16 lanes of one half-warp) ----
    const float* bptr = bias + h * 4096;
    #pragma unroll
    for (int i = 0; i < 4; ++i) {
        float4 b4 = *(const float4*)(bptr + (ty * 4 + i) * 64 + tx * 4);
        acc[i][0] += b4.x; acc[i][1] += b4.y;
        acc[i][2] += b4.z; acc[i][3] += b4.w;
        float m = fmaxf(fmaxf(acc[i][0], acc[i][1]), fmaxf(acc[i][2], acc[i][3]));
        m = fmaxf(m, __shfl_xor_sync(0xffffffffu, m, 1));
        m = fmaxf(m, __shfl_xor_sync(0xffffffffu, m, 2));
        m = fmaxf(m, __shfl_xor_sync(0xffffffffu, m, 4));
        m = fmaxf(m, __shfl_xor_sync(0xffffffffu, m, 8));
        float s = 0.f;
        #pragma unroll
        for (int j = 0; j < 4; ++j) { acc[i][j] = __expf(acc[i][j] - m); s += acc[i][j]; }
        s += __shfl_xor_sync(0xffffffffu, s, 1);
        s += __shfl_xor_sync(0xffffffffu, s, 2);
        s += __shfl_xor_sync(0xffffffffu, s, 4);
        s += __shfl_xor_sync(0xffffffffu, s, 8);
        float inv = 1.0f / s;
        #pragma unroll
        for (int j = 0; j < 4; ++j)
            Ps[tx * 4 + j][ty * 4 + i] = acc[i][j] * inv;   // store P^T
    }
    __syncthreads();

    // ---- O = P V : 2x4 micro-tile per thread (64x32 output) ----
    const int i0 = (t >> 3) * 2;    // query rows
    const int d0 = (t & 7) * 4;     // head dims
    float o[2][4] = {};
    #pragma unroll 4
    for (int j = 0; j < 64; ++j) {
        float2 a = *(const float2*)(&Ps[j][i0]);
        float4 v = *(const float4*)(&Vs[j][d0]);
        o[0][0] = fmaf(a.x, v.x, o[0][0]); o[0][1] = fmaf(a.x, v.y, o[0][1]);
        o[0][2] = fmaf(a.x, v.z, o[0][2]); o[0][3] = fmaf(a.x, v.w, o[0][3]);
        o[1][0] = fmaf(a.y, v.x, o[1][0]); o[1][1] = fmaf(a.y, v.y, o[1][1]);
        o[1][2] = fmaf(a.y, v.z, o[1][2]); o[1][3] = fmaf(a.y, v.w, o[1][3]);
    }
    #pragma unroll
    for (int i = 0; i < 2; ++i) {
        int p  = i0 + i;
        int r  = wh * 8 + (p >> 3);
        int cc = ww * 8 + (p & 7);
        size_t tok = (size_t)((b << 16) + r * 256 + cc);
        float4 o4 = make_float4(o[i][0], o[i][1], o[i][2], o[i][3]);
        *(float4*)(out + tok * C_DIM + h * HD + d0) = o4;
    }
}

// ---------------------------------------------------------------------------
// Launch
// Inputs (metadata order): x, qkv_w, qkv_b, proj_w, proj_b, bias, H, W
// ---------------------------------------------------------------------------
extern "C" void kernel_launch(void* const* d_in, const int* in_sizes, int n_in,
                              void* d_out, int out_size)
{
    (void)in_sizes; (void)n_in; (void)out_size;
    const float* x      = (const float*)d_in[0];
    const float* qkv_w  = (const float*)d_in[1];
    const float* qkv_b  = (const float*)d_in[2];
    const float* proj_w = (const float*)d_in[3];
    const float* proj_b = (const float*)d_in[4];
    const float* bias   = (const float*)d_in[5];
    float* out = (float*)d_out;

    float* qkv_buf = nullptr;
    float* att_buf = nullptr;
    cudaGetSymbolAddress((void**)&qkv_buf, g_qkv);
    cudaGetSymbolAddress((void**)&att_buf, g_att);

    // 1) QKV projection: [262144,192] @ [576,192]^T + b -> [262144,576]
    gemm_nt_kernel<<<dim3(M_TOK / 64, QKV_N / 64), 256>>>(
        x, qkv_w, qkv_b, qkv_buf, M_TOK, QKV_N, C_DIM);

    // 2) Window attention -> [262144,192] token-major
    attn_kernel<<<dim3(NWIN, NHEAD), 256>>>(qkv_buf, bias, att_buf);

    // 3) Output projection: [262144,192] @ [192,192]^T + b -> d_out
    gemm_nt_kernel<<<dim3(M_TOK / 64, C_DIM / 64), 256>>>(
        att_buf, proj_w, proj_b, out, M_TOK, C_DIM, C_DIM);
}

// round 3
// speedup vs baseline: 1.8904x; 1.8904x over previous
#include <cuda_runtime.h>
#include <cuda_bf16.h>
#include <cstdint>

// Problem constants: B=4, H=W=256, C=192, WS=8, NH=6
#define M_TOK   262144
#define C_DIM   192
#define NHEAD   6
#define HD      32
#define NWIN    4096
#define QKV_N   576
#define KDIM    192

// Scratch (allocation-free rule)
__device__ float g_qkv[(size_t)M_TOK * QKV_N];
__device__ float g_att[(size_t)M_TOK * C_DIM];

__device__ __forceinline__ uint32_t smaddr(const void* p) {
    return (uint32_t)__cvta_generic_to_shared(p);
}

__device__ __forceinline__ void ldm4(uint32_t* r, uint32_t addr) {
    asm volatile("ldmatrix.sync.aligned.m8n8.x4.shared.b16 {%0,%1,%2,%3}, [%4];"
                 : "=r"(r[0]), "=r"(r[1]), "=r"(r[2]), "=r"(r[3]) : "r"(addr));
}

__device__ __forceinline__ void mma16816(float* c, const uint32_t* a, const uint32_t* b) {
    asm volatile("mma.sync.aligned.m16n8k16.row.col.f32.bf16.bf16.f32 "
                 "{%0,%1,%2,%3}, {%4,%5,%6,%7}, {%8,%9}, {%0,%1,%2,%3};"
                 : "+f"(c[0]), "+f"(c[1]), "+f"(c[2]), "+f"(c[3])
                 : "r"(a[0]), "r"(a[1]), "r"(a[2]), "r"(a[3]),
                   "r"(b[0]), "r"(b[1]));
}

// split one float into hi/lo bf16 and pack pairs
__device__ __forceinline__ void split2(float x, float y, uint32_t& hp, uint32_t& lp) {
    __nv_bfloat16 hx = __float2bfloat16(x);
    __nv_bfloat16 hy = __float2bfloat16(y);
    __nv_bfloat16 lx = __float2bfloat16(x - __bfloat162float(hx));
    __nv_bfloat16 ly = __float2bfloat16(y - __bfloat162float(hy));
    hp = (uint32_t)__bfloat16_as_ushort(hx) | ((uint32_t)__bfloat16_as_ushort(hy) << 16);
    lp = (uint32_t)__bfloat16_as_ushort(lx) | ((uint32_t)__bfloat16_as_ushort(ly) << 16);
}

// ---------------------------------------------------------------------------
// HMMA GEMM: C[M,Ntot] = A[M,192] @ W[Ntot,192]^T + bias, 3-way bf16 split.
// BM=128, BN=64, BK=32, 256 threads, warp tile 32x32.
// ---------------------------------------------------------------------------
__global__ void __launch_bounds__(256) gemm_mma(
    const float* __restrict__ A, const float* __restrict__ W,
    const float* __restrict__ Bias, float* __restrict__ C,
    int Ntot)
{
    __shared__ unsigned short Ah[128][40];
    __shared__ unsigned short Al[128][40];
    __shared__ unsigned short Bh[64][40];
    __shared__ unsigned short Bl[64][40];

    const int tid  = threadIdx.x;
    const int wid  = tid >> 5;
    const int lane = tid & 31;
    const int wm   = (wid & 3) * 32;
    const int wn   = (wid >> 2) * 32;
    const int bm   = blockIdx.y * 128;
    const int bn   = blockIdx.x * 64;

    float acc[2][4][4] = {};

    // ldmatrix lane mappings
    const int aRow = lane & 15;
    const int aK   = (lane >> 4) * 8;
    const int bRow = (lane & 7) + ((lane >> 4) << 3);
    const int bK   = ((lane >> 3) & 1) * 8;

    const int sr = tid >> 3;            // staging row 0..31? no: see below
    const int sc = (tid & 7) * 4;       // staging k-chunk

    for (int k0 = 0; k0 < KDIM; k0 += 32) {
        __syncthreads();
        // stage A: 128 rows x 32 k  (4 x float4 per thread)
        #pragma unroll
        for (int it = 0; it < 4; ++it) {
            int r = sr + it * 32;
            float4 v = *(const float4*)(A + (size_t)(bm + r) * KDIM + k0 + sc);
            uint32_t h01, l01, h23, l23;
            split2(v.x, v.y, h01, l01);
            split2(v.z, v.w, h23, l23);
            *(uint2*)&Ah[r][sc] = make_uint2(h01, h23);
            *(uint2*)&Al[r][sc] = make_uint2(l01, l23);
        }
        // stage B: 64 rows x 32 k  (2 x float4 per thread)
        #pragma unroll
        for (int it = 0; it < 2; ++it) {
            int r = sr + it * 32;
            float4 v = *(const float4*)(W + (size_t)(bn + r) * KDIM + k0 + sc);
            uint32_t h01, l01, h23, l23;
            split2(v.x, v.y, h01, l01);
            split2(v.z, v.w, h23, l23);
            *(uint2*)&Bh[r][sc] = make_uint2(h01, h23);
            *(uint2*)&Bl[r][sc] = make_uint2(l01, l23);
        }
        __syncthreads();

        #pragma unroll
        for (int ks = 0; ks < 32; ks += 16) {
            uint32_t ahf[2][4], alf[2][4], bhf[2][4], blf[2][4];
            #pragma unroll
            for (int t = 0; t < 2; ++t) {
                ldm4(ahf[t], smaddr(&Ah[wm + t * 16 + aRow][ks + aK]));
                ldm4(alf[t], smaddr(&Al[wm + t * 16 + aRow][ks + aK]));
                ldm4(bhf[t], smaddr(&Bh[wn + t * 16 + bRow][ks + bK]));
                ldm4(blf[t], smaddr(&Bl[wn + t * 16 + bRow][ks + bK]));
            }
            #pragma unroll
            for (int mt = 0; mt < 2; ++mt)
                #pragma unroll
                for (int nt = 0; nt < 4; ++nt) {
                    const uint32_t* bh = &bhf[nt >> 1][(nt & 1) * 2];
                    const uint32_t* bl = &blf[nt >> 1][(nt & 1) * 2];
                    mma16816(acc[mt][nt], ahf[mt], bh);   // hi*hi
                    mma16816(acc[mt][nt], ahf[mt], bl);   // hi*lo
                    mma16816(acc[mt][nt], alf[mt], bh);   // lo*hi
                }
        }
    }

    // epilogue: bias + store (float2 per fragment row)
    const int row0 = bm + wm + (lane >> 2);
    const int col0 = bn + wn + (lane & 3) * 2;
    #pragma unroll
    for (int nt = 0; nt < 4; ++nt) {
        float2 bb = *(const float2*)(Bias + col0 + nt * 8);
        #pragma unroll
        for (int mt = 0; mt < 2; ++mt) {
            int r = row0 + mt * 16;
            float* c = acc[mt][nt];
            *(float2*)(C + (size_t)r * Ntot + col0 + nt * 8) =
                make_float2(c[0] + bb.x, c[1] + bb.y);
            *(float2*)(C + (size_t)(r + 8) * Ntot + col0 + nt * 8) =
                make_float2(c[2] + bb.x, c[3] + bb.y);
        }
    }
}

// ---------------------------------------------------------------------------
// Window attention (unchanged, passed in round 1)
// ---------------------------------------------------------------------------
__global__ void __launch_bounds__(256) attn_kernel(
    const float* __restrict__ qkv, const float* __restrict__ bias,
    float* __restrict__ out)
{
    __shared__ float Qs[32][68];
    __shared__ float Ks[32][68];
    __shared__ float Vs[64][32];
    __shared__ float Ps[64][68];

    const int w  = blockIdx.x;
    const int h  = blockIdx.y;
    const int b  = w >> 10;
    const int wi = w & 1023;
    const int wh = wi >> 5;
    const int ww = wi & 31;
    const int t  = threadIdx.x;

    const float scale = 0.17677669529663687f;

    #pragma unroll
    for (int it = 0; it < 2; ++it) {
        int idx = t + it * 256;
        int p = idx >> 3;
        int c = idx & 7;
        int r  = wh * 8 + (p >> 3);
        int cc = ww * 8 + (p & 7);
        size_t tok = (size_t)((b << 16) + r * 256 + cc);
        const float* base = qkv + tok * QKV_N + h * HD + c * 4;
        float4 q4 = *(const float4*)(base);
        float4 k4 = *(const float4*)(base + 192);
        float4 v4 = *(const float4*)(base + 384);
        int d = c * 4;
        Qs[d + 0][p] = q4.x * scale; Qs[d + 1][p] = q4.y * scale;
        Qs[d + 2][p] = q4.z * scale; Qs[d + 3][p] = q4.w * scale;
        Ks[d + 0][p] = k4.x; Ks[d + 1][p] = k4.y;
        Ks[d + 2][p] = k4.z; Ks[d + 3][p] = k4.w;
        *(float4*)(&Vs[p][d]) = v4;
    }
    __syncthreads();

    const int tx = t & 15;
    const int ty = t >> 4;
    float acc[4][4] = {};
    #pragma unroll
    for (int d = 0; d < 32; ++d) {
        float4 av = *(const float4*)(&Qs[d][ty * 4]);
        float4 bv = *(const float4*)(&Ks[d][tx * 4]);
        float af[4] = {av.x, av.y, av.z, av.w};
        float bf[4] = {bv.x, bv.y, bv.z, bv.w};
        #pragma unroll
        for (int i = 0; i < 4; ++i)
            #pragma unroll
            for (int j = 0; j < 4; ++j)
                acc[i][j] = fmaf(af[i], bf[j], acc[i][j]);
    }

    const float* bptr = bias + h * 4096;
    #pragma unroll
    for (int i = 0; i < 4; ++i) {
        float4 b4 = *(const float4*)(bptr + (ty * 4 + i) * 64 + tx * 4);
        acc[i][0] += b4.x; acc[i][1] += b4.y;
        acc[i][2] += b4.z; acc[i][3] += b4.w;
        float m = fmaxf(fmaxf(acc[i][0], acc[i][1]), fmaxf(acc[i][2], acc[i][3]));
        m = fmaxf(m, __shfl_xor_sync(0xffffffffu, m, 1));
        m = fmaxf(m, __shfl_xor_sync(0xffffffffu, m, 2));
        m = fmaxf(m, __shfl_xor_sync(0xffffffffu, m, 4));
        m = fmaxf(m, __shfl_xor_sync(0xffffffffu, m, 8));
        float s = 0.f;
        #pragma unroll
        for (int j = 0; j < 4; ++j) { acc[i][j] = __expf(acc[i][j] - m); s += acc[i][j]; }
        s += __shfl_xor_sync(0xffffffffu, s, 1);
        s += __shfl_xor_sync(0xffffffffu, s, 2);
        s += __shfl_xor_sync(0xffffffffu, s, 4);
        s += __shfl_xor_sync(0xffffffffu, s, 8);
        float inv = 1.0f / s;
        #pragma unroll
        for (int j = 0; j < 4; ++j)
            Ps[tx * 4 + j][ty * 4 + i] = acc[i][j] * inv;
    }
    __syncthreads();

    const int i0 = (t >> 3) * 2;
    const int d0 = (t & 7) * 4;
    float o[2][4] = {};
    #pragma unroll 4
    for (int j = 0; j < 64; ++j) {
        float2 a = *(const float2*)(&Ps[j][i0]);
        float4 v = *(const float4*)(&Vs[j][d0]);
        o[0][0] = fmaf(a.x, v.x, o[0][0]); o[0][1] = fmaf(a.x, v.y, o[0][1]);
        o[0][2] = fmaf(a.x, v.z, o[0][2]); o[0][3] = fmaf(a.x, v.w, o[0][3]);
        o[1][0] = fmaf(a.y, v.x, o[1][0]); o[1][1] = fmaf(a.y, v.y, o[1][1]);
        o[1][2] = fmaf(a.y, v.z, o[1][2]); o[1][3] = fmaf(a.y, v.w, o[1][3]);
    }
    #pragma unroll
    for (int i = 0; i < 2; ++i) {
        int p  = i0 + i;
        int r  = wh * 8 + (p >> 3);
        int cc = ww * 8 + (p & 7);
        size_t tok = (size_t)((b << 16) + r * 256 + cc);
        float4 o4 = make_float4(o[i][0], o[i][1], o[i][2], o[i][3]);
        *(float4*)(out + tok * C_DIM + h * HD + d0) = o4;
    }
}

// ---------------------------------------------------------------------------
// Launch: x, qkv_w, qkv_b, proj_w, proj_b, bias, H, W
// ---------------------------------------------------------------------------
extern "C" void kernel_launch(void* const* d_in, const int* in_sizes, int n_in,
                              void* d_out, int out_size)
{
    (void)in_sizes; (void)n_in; (void)out_size;
    const float* x      = (const float*)d_in[0];
    const float* qkv_w  = (const float*)d_in[1];
    const float* qkv_b  = (const float*)d_in[2];
    const float* proj_w = (const float*)d_in[3];
    const float* proj_b = (const float*)d_in[4];
    const float* bias   = (const float*)d_in[5];
    float* out = (float*)d_out;

    float* qkv_buf = nullptr;
    float* att_buf = nullptr;
    cudaGetSymbolAddress((void**)&qkv_buf, g_qkv);
    cudaGetSymbolAddress((void**)&att_buf, g_att);

    // 1) QKV projection: N=576 (grid.x fastest -> A L2 reuse across 9 N-tiles)
    gemm_mma<<<dim3(QKV_N / 64, M_TOK / 128), 256>>>(x, qkv_w, qkv_b, qkv_buf, QKV_N);

    // 2) Window attention
    attn_kernel<<<dim3(NWIN, NHEAD), 256>>>(qkv_buf, bias, att_buf);

    // 3) Output projection: N=192
    gemm_mma<<<dim3(C_DIM / 64, M_TOK / 128), 256>>>(att_buf, proj_w, proj_b, out, C_DIM);
}

// round 4
// speedup vs baseline: 2.2101x; 1.1692x over previous
#include <cuda_runtime.h>
#include <cuda_fp16.h>
#include <cstdint>

// Problem constants: B=4, H=W=256, C=192, WS=8, NH=6
#define M_TOK   262144
#define C_DIM   192
#define NHEAD   6
#define HD      32
#define NWIN    4096
#define QKV_N   576
#define KDIM    192

// Scratch (allocation-free rule)
__device__ float  g_qkv[(size_t)M_TOK * QKV_N];     // fp32 qkv for attention
__device__ __half g_xf[(size_t)M_TOK * KDIM];       // x in fp16
__device__ __half g_att[(size_t)M_TOK * C_DIM];     // attention out in fp16
__device__ __half g_wqh[(size_t)QKV_N * KDIM];      // qkv_w hi
__device__ __half g_wql[(size_t)QKV_N * KDIM];      // qkv_w lo
__device__ __half g_wph[(size_t)C_DIM * KDIM];      // proj_w hi
__device__ __half g_wpl[(size_t)C_DIM * KDIM];      // proj_w lo

__device__ __forceinline__ uint32_t smaddr(const void* p) {
    return (uint32_t)__cvta_generic_to_shared(p);
}
__device__ __forceinline__ void ldm4(uint32_t* r, uint32_t addr) {
    asm volatile("ldmatrix.sync.aligned.m8n8.x4.shared.b16 {%0,%1,%2,%3}, [%4];"
                 : "=r"(r[0]), "=r"(r[1]), "=r"(r[2]), "=r"(r[3]) : "r"(addr));
}
__device__ __forceinline__ void mma16816(float* c, const uint32_t* a, const uint32_t* b) {
    asm volatile("mma.sync.aligned.m16n8k16.row.col.f32.f16.f16.f32 "
                 "{%0,%1,%2,%3}, {%4,%5,%6,%7}, {%8,%9}, {%0,%1,%2,%3};"
                 : "+f"(c[0]), "+f"(c[1]), "+f"(c[2]), "+f"(c[3])
                 : "r"(a[0]), "r"(a[1]), "r"(a[2]), "r"(a[3]),
                   "r"(b[0]), "r"(b[1]));
}
__device__ __forceinline__ void cpa16(void* smem_dst, const void* gmem_src) {
    asm volatile("cp.async.cg.shared.global [%0], [%1], 16;"
                 :: "r"(smaddr(smem_dst)), "l"(gmem_src));
}

// ---------------------------------------------------------------------------
// Converters
// ---------------------------------------------------------------------------
__global__ void conv_x_kernel(const float* __restrict__ x, __half* __restrict__ xf, int n4) {
    int i = blockIdx.x * blockDim.x + threadIdx.x;
    if (i < n4) {
        float4 v = *(const float4*)(x + (size_t)i * 4);
        __half2 a = __floats2half2_rn(v.x, v.y);
        __half2 b = __floats2half2_rn(v.z, v.w);
        *(uint2*)(xf + (size_t)i * 4) = make_uint2(
            *(uint32_t*)&a, *(uint32_t*)&b);
    }
}
__global__ void conv_w_kernel(const float* __restrict__ w, __half* __restrict__ wh,
                              __half* __restrict__ wl, int n) {
    int i = blockIdx.x * blockDim.x + threadIdx.x;
    if (i < n) {
        float v = w[i];
        __half h = __float2half_rn(v);
        wh[i] = h;
        wl[i] = __float2half_rn(v - __half2float(h));
    }
}

// ---------------------------------------------------------------------------
// fp16 HMMA GEMM, 2-pass weight split: C = A @ (Wh+Wl)^T + bias
// BM=128, BN=64, BK=32, 256 threads, warp tile 32x32, cp.async double-buffer.
// ---------------------------------------------------------------------------
__global__ void __launch_bounds__(256) gemm_f16(
    const __half* __restrict__ A, const __half* __restrict__ Wh,
    const __half* __restrict__ Wl, const float* __restrict__ Bias,
    float* __restrict__ C, int Ntot)
{
    __shared__ __half As[2][128][40];
    __shared__ __half Bhs[2][64][40];
    __shared__ __half Bls[2][64][40];

    const int tid  = threadIdx.x;
    const int wid  = tid >> 5;
    const int lane = tid & 31;
    const int wm   = (wid & 3) * 32;
    const int wn   = (wid >> 2) * 32;
    const int bm   = blockIdx.y * 128;
    const int bn   = blockIdx.x * 64;

    // staging mapping: 16B chunks (8 halves)
    const int arow0 = tid >> 2;           // A chunk set 1: rows 0..63
    const int acol  = (tid & 3) * 8;      // k-offset within BK
    const int brow  = tid >> 2;           // B rows 0..63

    float acc[2][4][4] = {};

    // ldmatrix lane mappings
    const int aRow = lane & 15;
    const int aK   = (lane >> 4) * 8;
    const int bRow = (lane & 7) + ((lane >> 4) << 3);
    const int bK   = ((lane >> 3) & 1) * 8;

    // ---- stage(it, buf) ----
    auto stage = [&](int it, int b) {
        int k0 = it * 32;
        const __half* Ab = A + (size_t)(bm + arow0) * KDIM + k0 + acol;
        cpa16(&As[b][arow0][acol],      Ab);
        cpa16(&As[b][arow0 + 64][acol], Ab + (size_t)64 * KDIM);
        const __half* Bhb = Wh + (size_t)(bn + brow) * KDIM + k0 + acol;
        const __half* Blb = Wl + (size_t)(bn + brow) * KDIM + k0 + acol;
        cpa16(&Bhs[b][brow][acol], Bhb);
        cpa16(&Bls[b][brow][acol], Blb);
    };

    stage(0, 0);
    asm volatile("cp.async.commit_group;" ::: "memory");

    int buf = 0;
    #pragma unroll 1
    for (int it = 0; it < 6; ++it) {
        if (it < 5) {
            stage(it + 1, buf ^ 1);
            asm volatile("cp.async.commit_group;" ::: "memory");
            asm volatile("cp.async.wait_group 1;" ::: "memory");
        } else {
            asm volatile("cp.async.wait_group 0;" ::: "memory");
        }
        __syncthreads();

        #pragma unroll
        for (int ks = 0; ks < 32; ks += 16) {
            uint32_t ahf[2][4], bhf[2][4], blf[2][4];
            #pragma unroll
            for (int t = 0; t < 2; ++t) {
                ldm4(ahf[t], smaddr(&As[buf][wm + t * 16 + aRow][ks + aK]));
                ldm4(bhf[t], smaddr(&Bhs[buf][wn + t * 16 + bRow][ks + bK]));
                ldm4(blf[t], smaddr(&Bls[buf][wn + t * 16 + bRow][ks + bK]));
            }
            #pragma unroll
            for (int mt = 0; mt < 2; ++mt)
                #pragma unroll
                for (int nt = 0; nt < 4; ++nt) {
                    mma16816(acc[mt][nt], ahf[mt], &bhf[nt >> 1][(nt & 1) * 2]);
                    mma16816(acc[mt][nt], ahf[mt], &blf[nt >> 1][(nt & 1) * 2]);
                }
        }
        __syncthreads();
        buf ^= 1;
    }

    // epilogue: bias + store
    const int row0 = bm + wm + (lane >> 2);
    const int col0 = bn + wn + (lane & 3) * 2;
    #pragma unroll
    for (int nt = 0; nt < 4; ++nt) {
        float2 bb = *(const float2*)(Bias + col0 + nt * 8);
        #pragma unroll
        for (int mt = 0; mt < 2; ++mt) {
            int r = row0 + mt * 16;
            float* c = acc[mt][nt];
            *(float2*)(C + (size_t)r * Ntot + col0 + nt * 8) =
                make_float2(c[0] + bb.x, c[1] + bb.y);
            *(float2*)(C + (size_t)(r + 8) * Ntot + col0 + nt * 8) =
                make_float2(c[2] + bb.x, c[3] + bb.y);
        }
    }
}

// ---------------------------------------------------------------------------
// Window attention: fp32 compute, fp16 output (feeds GEMM2's A operand).
// ---------------------------------------------------------------------------
__global__ void __launch_bounds__(256) attn_kernel(
    const float* __restrict__ qkv, const float* __restrict__ bias,
    __half* __restrict__ out)
{
    __shared__ float Qs[32][68];
    __shared__ float Ks[32][68];
    __shared__ float Vs[64][32];
    __shared__ float Ps[64][68];

    const int w  = blockIdx.x;
    const int h  = blockIdx.y;
    const int b  = w >> 10;
    const int wi = w & 1023;
    const int wh = wi >> 5;
    const int ww = wi & 31;
    const int t  = threadIdx.x;

    const float scale = 0.17677669529663687f;

    #pragma unroll
    for (int it = 0; it < 2; ++it) {
        int idx = t + it * 256;
        int p = idx >> 3;
        int c = idx & 7;
        int r  = wh * 8 + (p >> 3);
        int cc = ww * 8 + (p & 7);
        size_t tok = (size_t)((b << 16) + r * 256 + cc);
        const float* base = qkv + tok * QKV_N + h * HD + c * 4;
        float4 q4 = *(const float4*)(base);
        float4 k4 = *(const float4*)(base + 192);
        float4 v4 = *(const float4*)(base + 384);
        int d = c * 4;
        Qs[d + 0][p] = q4.x * scale; Qs[d + 1][p] = q4.y * scale;
        Qs[d + 2][p] = q4.z * scale; Qs[d + 3][p] = q4.w * scale;
        Ks[d + 0][p] = k4.x; Ks[d + 1][p] = k4.y;
        Ks[d + 2][p] = k4.z; Ks[d + 3][p] = k4.w;
        *(float4*)(&Vs[p][d]) = v4;
    }
    __syncthreads();

    const int tx = t & 15;
    const int ty = t >> 4;
    float acc[4][4] = {};
    #pragma unroll
    for (int d = 0; d < 32; ++d) {
        float4 av = *(const float4*)(&Qs[d][ty * 4]);
        float4 bv = *(const float4*)(&Ks[d][tx * 4]);
        float af[4] = {av.x, av.y, av.z, av.w};
        float bf[4] = {bv.x, bv.y, bv.z, bv.w};
        #pragma unroll
        for (int i = 0; i < 4; ++i)
            #pragma unroll
            for (int j = 0; j < 4; ++j)
                acc[i][j] = fmaf(af[i], bf[j], acc[i][j]);
    }

    const float* bptr = bias + h * 4096;
    #pragma unroll
    for (int i = 0; i < 4; ++i) {
        float4 b4 = *(const float4*)(bptr + (ty * 4 + i) * 64 + tx * 4);
        acc[i][0] += b4.x; acc[i][1] += b4.y;
        acc[i][2] += b4.z; acc[i][3] += b4.w;
        float m = fmaxf(fmaxf(acc[i][0], acc[i][1]), fmaxf(acc[i][2], acc[i][3]));
        m = fmaxf(m, __shfl_xor_sync(0xffffffffu, m, 1));
        m = fmaxf(m, __shfl_xor_sync(0xffffffffu, m, 2));
        m = fmaxf(m, __shfl_xor_sync(0xffffffffu, m, 4));
        m = fmaxf(m, __shfl_xor_sync(0xffffffffu, m, 8));
        float s = 0.f;
        #pragma unroll
        for (int j = 0; j < 4; ++j) { acc[i][j] = __expf(acc[i][j] - m); s += acc[i][j]; }
        s += __shfl_xor_sync(0xffffffffu, s, 1);
        s += __shfl_xor_sync(0xffffffffu, s, 2);
        s += __shfl_xor_sync(0xffffffffu, s, 4);
        s += __shfl_xor_sync(0xffffffffu, s, 8);
        float inv = 1.0f / s;
        #pragma unroll
        for (int j = 0; j < 4; ++j)
            Ps[tx * 4 + j][ty * 4 + i] = acc[i][j] * inv;
    }
    __syncthreads();

    const int i0 = (t >> 3) * 2;
    const int d0 = (t & 7) * 4;
    float o[2][4] = {};
    #pragma unroll 4
    for (int j = 0; j < 64; ++j) {
        float2 a = *(const float2*)(&Ps[j][i0]);
        float4 v = *(const float4*)(&Vs[j][d0]);
        o[0][0] = fmaf(a.x, v.x, o[0][0]); o[0][1] = fmaf(a.x, v.y, o[0][1]);
        o[0][2] = fmaf(a.x, v.z, o[0][2]); o[0][3] = fmaf(a.x, v.w, o[0][3]);
        o[1][0] = fmaf(a.y, v.x, o[1][0]); o[1][1] = fmaf(a.y, v.y, o[1][1]);
        o[1][2] = fmaf(a.y, v.z, o[1][2]); o[1][3] = fmaf(a.y, v.w, o[1][3]);
    }
    #pragma unroll
    for (int i = 0; i < 2; ++i) {
        int p  = i0 + i;
        int r  = wh * 8 + (p >> 3);
        int cc = ww * 8 + (p & 7);
        size_t tok = (size_t)((b << 16) + r * 256 + cc);
        __half2 p0 = __floats2half2_rn(o[i][0], o[i][1]);
        __half2 p1 = __floats2half2_rn(o[i][2], o[i][3]);
        *(uint2*)(out + tok * C_DIM + h * HD + d0) =
            make_uint2(*(uint32_t*)&p0, *(uint32_t*)&p1);
    }
}

// ---------------------------------------------------------------------------
// Launch: x, qkv_w, qkv_b, proj_w, proj_b, bias, H, W
// ---------------------------------------------------------------------------
extern "C" void kernel_launch(void* const* d_in, const int* in_sizes, int n_in,
                              void* d_out, int out_size)
{
    (void)in_sizes; (void)n_in; (void)out_size;
    const float* x      = (const float*)d_in[0];
    const float* qkv_w  = (const float*)d_in[1];
    const float* qkv_b  = (const float*)d_in[2];
    const float* proj_w = (const float*)d_in[3];
    const float* proj_b = (const float*)d_in[4];
    const float* bias   = (const float*)d_in[5];
    float* out = (float*)d_out;

    float  *qkv_buf, *dummy;
    __half *xf, *att, *wqh, *wql, *wph, *wpl;
    cudaGetSymbolAddress((void**)&qkv_buf, g_qkv);
    cudaGetSymbolAddress((void**)&xf,  g_xf);
    cudaGetSymbolAddress((void**)&att, g_att);
    cudaGetSymbolAddress((void**)&wqh, g_wqh);
    cudaGetSymbolAddress((void**)&wql, g_wql);
    cudaGetSymbolAddress((void**)&wph, g_wph);
    cudaGetSymbolAddress((void**)&wpl, g_wpl);
    (void)dummy;

    // 0) conversions
    conv_x_kernel<<<(M_TOK * KDIM / 4 + 255) / 256, 256>>>(x, xf, M_TOK * KDIM / 4);
    conv_w_kernel<<<(QKV_N * KDIM + 255) / 256, 256>>>(qkv_w, wqh, wql, QKV_N * KDIM);
    conv_w_kernel<<<(C_DIM * KDIM + 255) / 256, 256>>>(proj_w, wph, wpl, C_DIM * KDIM);

    // 1) QKV projection (N fastest -> A panel L2 reuse across 9 N-tiles)
    gemm_f16<<<dim3(QKV_N / 64, M_TOK / 128), 256>>>(xf, wqh, wql, qkv_b, qkv_buf, QKV_N);

    // 2) Window attention (fp32 in, fp16 out)
    attn_kernel<<<dim3(NWIN, NHEAD), 256>>>(qkv_buf, bias, att);

    // 3) Output projection
    gemm_f16<<<dim3(C_DIM / 64, M_TOK / 128), 256>>>(att, wph, wpl, proj_b, out, C_DIM);
}

// round 7
// speedup vs baseline: 3.3083x; 1.4969x over previous
#include <cuda_runtime.h>
#include <cuda_fp16.h>
#include <cstdint>

// Problem constants: B=4, H=W=256, C=192, WS=8, NH=6
#define M_TOK   262144
#define C_DIM   192
#define NHEAD   6
#define HD      32
#define NWIN    4096
#define QKV_N   576
#define KDIM    192
#define LOG2E   1.4426950408889634f
#define QSCALE  0.17677669529663687f

// Scratch (allocation-free rule)
__device__ __half g_qkvh[(size_t)M_TOK * QKV_N];    // qkv fp16 (Q pre-scaled)
__device__ __half g_xf[(size_t)M_TOK * KDIM];       // x fp16
__device__ __half g_att[(size_t)M_TOK * C_DIM];     // attention out fp16
__device__ __half g_wqh[(size_t)QKV_N * KDIM];
__device__ __half g_wql[(size_t)QKV_N * KDIM];
__device__ __half g_wph[(size_t)C_DIM * KDIM];
__device__ __half g_wpl[(size_t)C_DIM * KDIM];
__device__ float  g_biasL[NHEAD * 64 * 64];         // bias * log2e

__device__ __forceinline__ uint32_t smaddr(const void* p) {
    return (uint32_t)__cvta_generic_to_shared(p);
}
__device__ __forceinline__ void ldm4(uint32_t* r, uint32_t addr) {
    asm volatile("ldmatrix.sync.aligned.m8n8.x4.shared.b16 {%0,%1,%2,%3}, [%4];"
                 : "=r"(r[0]), "=r"(r[1]), "=r"(r[2]), "=r"(r[3]) : "r"(addr));
}
__device__ __forceinline__ void ldm4t(uint32_t* r, uint32_t addr) {
    asm volatile("ldmatrix.sync.aligned.m8n8.x4.trans.shared.b16 {%0,%1,%2,%3}, [%4];"
                 : "=r"(r[0]), "=r"(r[1]), "=r"(r[2]), "=r"(r[3]) : "r"(addr));
}
__device__ __forceinline__ void mma16816(float* c, const uint32_t* a, const uint32_t* b) {
    asm volatile("mma.sync.aligned.m16n8k16.row.col.f32.f16.f16.f32 "
                 "{%0,%1,%2,%3}, {%4,%5,%6,%7}, {%8,%9}, {%0,%1,%2,%3};"
                 : "+f"(c[0]), "+f"(c[1]), "+f"(c[2]), "+f"(c[3])
                 : "r"(a[0]), "r"(a[1]), "r"(a[2]), "r"(a[3]),
                   "r"(b[0]), "r"(b[1]));
}
__device__ __forceinline__ void cpa16(void* smem_dst, const void* gmem_src) {
    asm volatile("cp.async.cg.shared.global [%0], [%1], 16;"
                 :: "r"(smaddr(smem_dst)), "l"(gmem_src));
}
__device__ __forceinline__ uint32_t exp2_h2(float hi, float lo) {
    uint32_t t, r;
    asm("cvt.rn.f16x2.f32 %0, %1, %2;" : "=r"(t) : "f"(hi), "f"(lo));
    asm("ex2.approx.f16x2 %0, %1;" : "=r"(r) : "r"(t));
    return r;
}

// ---------------------------------------------------------------------------
// Converters
// ---------------------------------------------------------------------------
__global__ void conv_x_kernel(const float* __restrict__ x, __half* __restrict__ xf, int n4) {
    int i = blockIdx.x * blockDim.x + threadIdx.x;
    if (i < n4) {
        float4 v = *(const float4*)(x + (size_t)i * 4);
        __half2 a = __floats2half2_rn(v.x, v.y);
        __half2 b = __floats2half2_rn(v.z, v.w);
        *(uint2*)(xf + (size_t)i * 4) = make_uint2(*(uint32_t*)&a, *(uint32_t*)&b);
    }
}
__global__ void conv_w_kernel(const float* __restrict__ w, __half* __restrict__ wh,
                              __half* __restrict__ wl, int n) {
    int i = blockIdx.x * blockDim.x + threadIdx.x;
    if (i < n) {
        float v = w[i];
        __half h = __float2half_rn(v);
        wh[i] = h;
        wl[i] = __float2half_rn(v - __half2float(h));
    }
}
__global__ void conv_bias_kernel(const float* __restrict__ b, float* __restrict__ bL, int n) {
    int i = blockIdx.x * blockDim.x + threadIdx.x;
    if (i < n) bL[i] = b[i] * LOG2E;
}

// ---------------------------------------------------------------------------
// fp16 HMMA GEMM, 2-pass weight split: C = A @ (Wh+Wl)^T + bias
// BM=128, BN=64, BK=32, 256 threads, warp tile 32x32, cp.async double-buffer.
// HOUT: write fp16 with per-column multiplier (cols < qthr scaled by qmul).
// ---------------------------------------------------------------------------
template<bool HOUT>
__global__ void __launch_bounds__(256) gemm_f16(
    const __half* __restrict__ A, const __half* __restrict__ Wh,
    const __half* __restrict__ Wl, const float* __restrict__ Bias,
    void* __restrict__ Cv, int Ntot, int qthr, float qmul)
{
    __shared__ __half As[2][128][40];
    __shared__ __half Bhs[2][64][40];
    __shared__ __half Bls[2][64][40];

    const int tid  = threadIdx.x;
    const int wid  = tid >> 5;
    const int lane = tid & 31;
    const int wm   = (wid & 3) * 32;
    const int wn   = (wid >> 2) * 32;
    const int bm   = blockIdx.y * 128;
    const int bn   = blockIdx.x * 64;

    const int arow0 = tid >> 2;
    const int acol  = (tid & 3) * 8;
    const int brow  = tid >> 2;

    float acc[2][4][4] = {};

    const int aRow = lane & 15;
    const int aK   = (lane >> 4) * 8;
    const int bRow = (lane & 7) + ((lane >> 4) << 3);
    const int bK   = ((lane >> 3) & 1) * 8;

    auto stage = [&](int it, int b) {
        int k0 = it * 32;
        const __half* Ab = A + (size_t)(bm + arow0) * KDIM + k0 + acol;
        cpa16(&As[b][arow0][acol],      Ab);
        cpa16(&As[b][arow0 + 64][acol], Ab + (size_t)64 * KDIM);
        cpa16(&Bhs[b][brow][acol], Wh + (size_t)(bn + brow) * KDIM + k0 + acol);
        cpa16(&Bls[b][brow][acol], Wl + (size_t)(bn + brow) * KDIM + k0 + acol);
    };

    stage(0, 0);
    asm volatile("cp.async.commit_group;" ::: "memory");

    int buf = 0;
    #pragma unroll 1
    for (int it = 0; it < 6; ++it) {
        if (it < 5) {
            stage(it + 1, buf ^ 1);
            asm volatile("cp.async.commit_group;" ::: "memory");
            asm volatile("cp.async.wait_group 1;" ::: "memory");
        } else {
            asm volatile("cp.async.wait_group 0;" ::: "memory");
        }
        __syncthreads();

        #pragma unroll
        for (int ks = 0; ks < 32; ks += 16) {
            uint32_t ahf[2][4], bhf[2][4], blf[2][4];
            #pragma unroll
            for (int t = 0; t < 2; ++t) {
                ldm4(ahf[t], smaddr(&As[buf][wm + t * 16 + aRow][ks + aK]));
                ldm4(bhf[t], smaddr(&Bhs[buf][wn + t * 16 + bRow][ks + bK]));
                ldm4(blf[t], smaddr(&Bls[buf][wn + t * 16 + bRow][ks + bK]));
            }
            #pragma unroll
            for (int mt = 0; mt < 2; ++mt)
                #pragma unroll
                for (int nt = 0; nt < 4; ++nt) {
                    mma16816(acc[mt][nt], ahf[mt], &bhf[nt >> 1][(nt & 1) * 2]);
                    mma16816(acc[mt][nt], ahf[mt], &blf[nt >> 1][(nt & 1) * 2]);
                }
        }
        __syncthreads();
        buf ^= 1;
    }

    const int row0 = bm + wm + (lane >> 2);
    const int col0 = bn + wn + (lane & 3) * 2;
    #pragma unroll
    for (int nt = 0; nt < 4; ++nt) {
        int col = col0 + nt * 8;
        float2 bb = *(const float2*)(Bias + col);
        float mlt = HOUT ? ((col < qthr) ? qmul : 1.0f) : 1.0f;
        #pragma unroll
        for (int mt = 0; mt < 2; ++mt) {
            int r = row0 + mt * 16;
            float* c = acc[mt][nt];
            if (HOUT) {
                __half* C = (__half*)Cv;
                __half2 o0 = __floats2half2_rn((c[0] + bb.x) * mlt, (c[1] + bb.y) * mlt);
                __half2 o1 = __floats2half2_rn((c[2] + bb.x) * mlt, (c[3] + bb.y) * mlt);
                *(__half2*)(C + (size_t)r * Ntot + col) = o0;
                *(__half2*)(C + (size_t)(r + 8) * Ntot + col) = o1;
            } else {
                float* C = (float*)Cv;
                *(float2*)(C + (size_t)r * Ntot + col) =
                    make_float2(c[0] + bb.x, c[1] + bb.y);
                *(float2*)(C + (size_t)(r + 8) * Ntot + col) =
                    make_float2(c[2] + bb.x, c[3] + bb.y);
            }
        }
    }
}

// ---------------------------------------------------------------------------
// HMMA flash-style window attention.
// Block = 1 window, 384 threads, 12 warps = (head h, 32-row half).
// qkv fp16 [tok][576], Q pre-scaled by scale*log2e. biasL = bias*log2e fp32.
// S (fp32 accum, log2-domain) -> P = exp2 (fp16, in registers) -> O = P V.
// ---------------------------------------------------------------------------
#define ATT_STRIDE 584
#define ATT_SMEM   (64 * ATT_STRIDE * 2)

__global__ void __launch_bounds__(384) attn_mma(
    const __half* __restrict__ qkv, const float* __restrict__ biasL,
    __half* __restrict__ out)
{
    extern __shared__ __half sm[];   // [64][584]

    const int w   = blockIdx.x;
    const int b   = w >> 10;
    const int wi  = w & 1023;
    const int whh = wi >> 5;
    const int www = wi & 31;
    const int tid  = threadIdx.x;
    const int wid  = tid >> 5;
    const int lane = tid & 31;
    const int h    = wid >> 1;
    const int r0   = (wid & 1) * 32;
    const int tokbase = b * 65536 + whh * 8 * 256 + www * 8;

    // ---- cooperative load: 64 tokens x 576 halves ----
    #pragma unroll
    for (int i = 0; i < 12; ++i) {
        int idx = tid + i * 384;
        int row = idx / 72;
        int j   = idx % 72;
        int tok = tokbase + (row >> 3) * 256 + (row & 7);
        cpa16(&sm[row * ATT_STRIDE + j * 8], qkv + (size_t)tok * QKV_N + j * 8);
    }
    asm volatile("cp.async.commit_group;" ::: "memory");
    asm volatile("cp.async.wait_group 0;" ::: "memory");
    __syncthreads();

    // ---- S = Q K^T + biasL (accumulator initialized from biasL) ----
    float sacc[2][8][4];
    const float* bL = biasL + h * 4096;
    #pragma unroll
    for (int mt = 0; mt < 2; ++mt) {
        int rr = r0 + mt * 16 + (lane >> 2);
        #pragma unroll
        for (int nt = 0; nt < 8; ++nt) {
            int cc = nt * 8 + (lane & 3) * 2;
            float2 x0 = *(const float2*)(bL + rr * 64 + cc);
            float2 x1 = *(const float2*)(bL + (rr + 8) * 64 + cc);
            sacc[mt][nt][0] = x0.x; sacc[mt][nt][1] = x0.y;
            sacc[mt][nt][2] = x1.x; sacc[mt][nt][3] = x1.y;
        }
    }

    #pragma unroll
    for (int ks = 0; ks < 32; ks += 16) {
        uint32_t af[2][4], bf[4][4];
        #pragma unroll
        for (int mt = 0; mt < 2; ++mt)
            ldm4(af[mt], smaddr(&sm[(r0 + mt * 16 + (lane & 15)) * ATT_STRIDE
                                    + h * HD + ks + (lane >> 4) * 8]));
        #pragma unroll
        for (int g = 0; g < 4; ++g)
            ldm4(bf[g], smaddr(&sm[(g * 16 + (lane & 7) + ((lane >> 4) & 1) * 8) * ATT_STRIDE
                                   + h * HD + 192 + ks + ((lane >> 3) & 1) * 8]));
        #pragma unroll
        for (int mt = 0; mt < 2; ++mt)
            #pragma unroll
            for (int nt = 0; nt < 8; ++nt)
                mma16816(sacc[mt][nt], af[mt], &bf[nt >> 1][(nt & 1) * 2]);
    }

    // ---- softmax: P = exp2(S) fp16 in registers; fp32 row sums ----
    uint32_t P[2][8], P8[2][8];
    float inv0[2], inv1[2];
    #pragma unroll
    for (int mt = 0; mt < 2; ++mt) {
        float s0 = 0.f, s1 = 0.f;
        #pragma unroll
        for (int nt = 0; nt < 8; ++nt) {
            P[mt][nt]  = exp2_h2(sacc[mt][nt][1], sacc[mt][nt][0]);
            P8[mt][nt] = exp2_h2(sacc[mt][nt][3], sacc[mt][nt][2]);
            float2 f0 = __half22float2(*(__half2*)&P[mt][nt]);
            float2 f1 = __half22float2(*(__half2*)&P8[mt][nt]);
            s0 += f0.x + f0.y;
            s1 += f1.x + f1.y;
        }
        s0 += __shfl_xor_sync(0xffffffffu, s0, 1);
        s0 += __shfl_xor_sync(0xffffffffu, s0, 2);
        s1 += __shfl_xor_sync(0xffffffffu, s1, 1);
        s1 += __shfl_xor_sync(0xffffffffu, s1, 2);
        inv0[mt] = 1.0f / s0;
        inv1[mt] = 1.0f / s1;
    }

    // ---- O = P V ----
    float oacc[2][4][4] = {};
    #pragma unroll
    for (int ks = 0; ks < 4; ++ks) {
        uint32_t vf[2][4];
        #pragma unroll
        for (int g = 0; g < 2; ++g)
            ldm4t(vf[g], smaddr(&sm[(ks * 16 + (lane & 15)) * ATT_STRIDE
                                    + h * HD + 384 + g * 16 + (lane >> 4) * 8]));
        #pragma unroll
        for (int mt = 0; mt < 2; ++mt) {
            uint32_t a[4] = {P[mt][2 * ks], P8[mt][2 * ks],
                             P[mt][2 * ks + 1], P8[mt][2 * ks + 1]};
            #pragma unroll
            for (int nt = 0; nt < 4; ++nt)
                mma16816(oacc[mt][nt], a, &vf[nt >> 1][(nt & 1) * 2]);
        }
    }

    // ---- normalize + store fp16 ----
    #pragma unroll
    for (int mt = 0; mt < 2; ++mt) {
        int rr  = r0 + mt * 16 + (lane >> 2);
        int tok0 = tokbase + (rr >> 3) * 256 + (rr & 7);
        int rr8 = rr + 8;
        int tok1 = tokbase + (rr8 >> 3) * 256 + (rr8 & 7);
        #pragma unroll
        for (int nt = 0; nt < 4; ++nt) {
            int d = h * HD + nt * 8 + (lane & 3) * 2;
            float* c = oacc[mt][nt];
            __half2 o0 = __floats2half2_rn(c[0] * inv0[mt], c[1] * inv0[mt]);
            __half2 o1 = __floats2half2_rn(c[2] * inv1[mt], c[3] * inv1[mt]);
            *(__half2*)(out + (size_t)tok0 * C_DIM + d) = o0;
            *(__half2*)(out + (size_t)tok1 * C_DIM + d) = o1;
        }
    }
}

// ---------------------------------------------------------------------------
// Launch: x, qkv_w, qkv_b, proj_w, proj_b, bias, H, W
// ---------------------------------------------------------------------------
extern "C" void kernel_launch(void* const* d_in, const int* in_sizes, int n_in,
                              void* d_out, int out_size)
{
    (void)in_sizes; (void)n_in; (void)out_size;
    const float* x      = (const float*)d_in[0];
    const float* qkv_w  = (const float*)d_in[1];
    const float* qkv_b  = (const float*)d_in[2];
    const float* proj_w = (const float*)d_in[3];
    const float* proj_b = (const float*)d_in[4];
    const float* bias   = (const float*)d_in[5];
    float* out = (float*)d_out;

    __half *qkvh, *xf, *att, *wqh, *wql, *wph, *wpl;
    float  *biasL;
    cudaGetSymbolAddress((void**)&qkvh, g_qkvh);
    cudaGetSymbolAddress((void**)&xf,   g_xf);
    cudaGetSymbolAddress((void**)&att,  g_att);
    cudaGetSymbolAddress((void**)&wqh,  g_wqh);
    cudaGetSymbolAddress((void**)&wql,  g_wql);
    cudaGetSymbolAddress((void**)&wph,  g_wph);
    cudaGetSymbolAddress((void**)&wpl,  g_wpl);
    cudaGetSymbolAddress((void**)&biasL, g_biasL);

    cudaFuncSetAttribute(attn_mma, cudaFuncAttributeMaxDynamicSharedMemorySize, ATT_SMEM);

    // 0) conversions
    conv_x_kernel<<<(M_TOK * KDIM / 4 + 255) / 256, 256>>>(x, xf, M_TOK * KDIM / 4);
    conv_w_kernel<<<(QKV_N * KDIM + 255) / 256, 256>>>(qkv_w, wqh, wql, QKV_N * KDIM);
    conv_w_kernel<<<(C_DIM * KDIM + 255) / 256, 256>>>(proj_w, wph, wpl, C_DIM * KDIM);
    conv_bias_kernel<<<(NHEAD * 4096 + 255) / 256, 256>>>(bias, biasL, NHEAD * 4096);

    // 1) QKV projection -> fp16, Q pre-scaled by scale*log2e
    gemm_f16<true><<<dim3(QKV_N / 64, M_TOK / 128), 256>>>(
        xf, wqh, wql, qkv_b, qkvh, QKV_N, 192, QSCALE * LOG2E);

    // 2) HMMA window attention (fp16 in/out)
    attn_mma<<<NWIN, 384, ATT_SMEM>>>(qkvh, biasL, att);

    // 3) Output projection -> fp32 d_out
    gemm_f16<false><<<dim3(C_DIM / 64, M_TOK / 128), 256>>>(
        att, wph, wpl, proj_b, out, C_DIM, 0, 1.0f);
}

// round 8
// speedup vs baseline: 4.4253x; 1.3376x over previous
#include <cuda_runtime.h>
#include <cuda_fp16.h>
#include <cstdint>

// Problem constants: B=4, H=W=256, C=192, WS=8, NH=6
#define M_TOK   262144
#define C_DIM   192
#define NHEAD   6
#define HD      32
#define NWIN    4096
#define QKV_N   576
#define KDIM    192
#define LOG2E   1.4426950408889634f
#define QSCALE  0.17677669529663687f

// Scratch (allocation-free rule)
__device__ __half g_qkvh[(size_t)M_TOK * QKV_N];    // qkv fp16 (Q pre-scaled)
__device__ __half g_xf[(size_t)M_TOK * KDIM];       // x fp16
__device__ __half g_att[(size_t)M_TOK * C_DIM];     // attention out fp16
__device__ __half g_wq[(size_t)QKV_N * KDIM];       // qkv_w fp16
__device__ __half g_wp[(size_t)C_DIM * KDIM];       // proj_w fp16
__device__ float  g_biasL[NHEAD * 64 * 64];         // bias * log2e

__device__ __forceinline__ uint32_t smaddr(const void* p) {
    return (uint32_t)__cvta_generic_to_shared(p);
}
__device__ __forceinline__ void ldm4(uint32_t* r, uint32_t addr) {
    asm volatile("ldmatrix.sync.aligned.m8n8.x4.shared.b16 {%0,%1,%2,%3}, [%4];"
                 : "=r"(r[0]), "=r"(r[1]), "=r"(r[2]), "=r"(r[3]) : "r"(addr));
}
__device__ __forceinline__ void ldm4t(uint32_t* r, uint32_t addr) {
    asm volatile("ldmatrix.sync.aligned.m8n8.x4.trans.shared.b16 {%0,%1,%2,%3}, [%4];"
                 : "=r"(r[0]), "=r"(r[1]), "=r"(r[2]), "=r"(r[3]) : "r"(addr));
}
__device__ __forceinline__ void mma16816(float* c, const uint32_t* a, const uint32_t* b) {
    asm volatile("mma.sync.aligned.m16n8k16.row.col.f32.f16.f16.f32 "
                 "{%0,%1,%2,%3}, {%4,%5,%6,%7}, {%8,%9}, {%0,%1,%2,%3};"
                 : "+f"(c[0]), "+f"(c[1]), "+f"(c[2]), "+f"(c[3])
                 : "r"(a[0]), "r"(a[1]), "r"(a[2]), "r"(a[3]),
                   "r"(b[0]), "r"(b[1]));
}
__device__ __forceinline__ void cpa16(void* smem_dst, const void* gmem_src) {
    asm volatile("cp.async.cg.shared.global [%0], [%1], 16;"
                 :: "r"(smaddr(smem_dst)), "l"(gmem_src));
}
__device__ __forceinline__ uint32_t exp2_h2(float hi, float lo) {
    uint32_t t, r;
    asm("cvt.rn.f16x2.f32 %0, %1, %2;" : "=r"(t) : "f"(hi), "f"(lo));
    asm("ex2.approx.f16x2 %0, %1;" : "=r"(r) : "r"(t));
    return r;
}

// ---------------------------------------------------------------------------
// Converters
// ---------------------------------------------------------------------------
__global__ void conv_f2h_kernel(const float* __restrict__ x, __half* __restrict__ xf, int n4) {
    int i = blockIdx.x * blockDim.x + threadIdx.x;
    if (i < n4) {
        float4 v = *(const float4*)(x + (size_t)i * 4);
        __half2 a = __floats2half2_rn(v.x, v.y);
        __half2 b = __floats2half2_rn(v.z, v.w);
        *(uint2*)(xf + (size_t)i * 4) = make_uint2(*(uint32_t*)&a, *(uint32_t*)&b);
    }
}
__global__ void conv_bias_kernel(const float* __restrict__ b, float* __restrict__ bL, int n) {
    int i = blockIdx.x * blockDim.x + threadIdx.x;
    if (i < n) bL[i] = b[i] * LOG2E;
}

// ---------------------------------------------------------------------------
// fp16 HMMA GEMM, single-pass weights, full-K single-stage tiles.
// BM=128, BN=64, K=192 fully resident, 256 threads, warp tile 32x32.
// HOUT: write fp16 with per-column multiplier (cols < qthr scaled by qmul).
// ---------------------------------------------------------------------------
#define GSTRIDE 200
#define GEMM_SMEM ((128 + 64) * GSTRIDE * 2)   // 76800 bytes

template<bool HOUT>
__global__ void __launch_bounds__(256, 2) gemm_f16(
    const __half* __restrict__ A, const __half* __restrict__ W,
    const float* __restrict__ Bias, void* __restrict__ Cv,
    int Ntot, int qthr, float qmul)
{
    extern __shared__ __half smemg[];
    __half (*As)[GSTRIDE] = (__half(*)[GSTRIDE])smemg;
    __half (*Bs)[GSTRIDE] = (__half(*)[GSTRIDE])(smemg + 128 * GSTRIDE);

    const int tid  = threadIdx.x;
    const int wid  = tid >> 5;
    const int lane = tid & 31;
    const int wm   = (wid & 3) * 32;
    const int wn   = (wid >> 2) * 32;
    const int bm   = blockIdx.y * 128;
    const int bn   = blockIdx.x * 64;

    // ---- single staging burst: A 128x192, B 64x192 (16B chunks) ----
    #pragma unroll
    for (int i = 0; i < 12; ++i) {
        int idx = tid + i * 256;          // 0..3071
        int row = idx / 24;
        int col = (idx % 24) * 8;
        cpa16(&As[row][col], A + (size_t)(bm + row) * KDIM + col);
    }
    #pragma unroll
    for (int i = 0; i < 6; ++i) {
        int idx = tid + i * 256;          // 0..1535
        int row = idx / 24;
        int col = (idx % 24) * 8;
        cpa16(&Bs[row][col], W + (size_t)(bn + row) * KDIM + col);
    }
    asm volatile("cp.async.commit_group;" ::: "memory");
    asm volatile("cp.async.wait_group 0;" ::: "memory");
    __syncthreads();

    float acc[2][4][4] = {};

    const int aRow = lane & 15;
    const int aK   = (lane >> 4) * 8;
    const int bRow = (lane & 7) + ((lane >> 4) << 3);
    const int bK   = ((lane >> 3) & 1) * 8;

    // ---- 12 k-steps, no syncs ----
    #pragma unroll
    for (int ks = 0; ks < KDIM; ks += 16) {
        uint32_t af[2][4], bf[2][4];
        #pragma unroll
        for (int t = 0; t < 2; ++t) {
            ldm4(af[t], smaddr(&As[wm + t * 16 + aRow][ks + aK]));
            ldm4(bf[t], smaddr(&Bs[wn + t * 16 + bRow][ks + bK]));
        }
        #pragma unroll
        for (int mt = 0; mt < 2; ++mt)
            #pragma unroll
            for (int nt = 0; nt < 4; ++nt)
                mma16816(acc[mt][nt], af[mt], &bf[nt >> 1][(nt & 1) * 2]);
    }

    // ---- epilogue ----
    const int row0 = bm + wm + (lane >> 2);
    const int col0 = bn + wn + (lane & 3) * 2;
    #pragma unroll
    for (int nt = 0; nt < 4; ++nt) {
        int col = col0 + nt * 8;
        float2 bb = *(const float2*)(Bias + col);
        float mlt = HOUT ? ((col < qthr) ? qmul : 1.0f) : 1.0f;
        #pragma unroll
        for (int mt = 0; mt < 2; ++mt) {
            int r = row0 + mt * 16;
            float* c = acc[mt][nt];
            if (HOUT) {
                __half* C = (__half*)Cv;
                __half2 o0 = __floats2half2_rn((c[0] + bb.x) * mlt, (c[1] + bb.y) * mlt);
                __half2 o1 = __floats2half2_rn((c[2] + bb.x) * mlt, (c[3] + bb.y) * mlt);
                *(__half2*)(C + (size_t)r * Ntot + col) = o0;
                *(__half2*)(C + (size_t)(r + 8) * Ntot + col) = o1;
            } else {
                float* C = (float*)Cv;
                *(float2*)(C + (size_t)r * Ntot + col) =
                    make_float2(c[0] + bb.x, c[1] + bb.y);
                *(float2*)(C + (size_t)(r + 8) * Ntot + col) =
                    make_float2(c[2] + bb.x, c[3] + bb.y);
            }
        }
    }
}

// ---------------------------------------------------------------------------
// HMMA flash-style window attention (unchanged from round 7).
// ---------------------------------------------------------------------------
#define ATT_STRIDE 584
#define ATT_SMEM   (64 * ATT_STRIDE * 2)

__global__ void __launch_bounds__(384) attn_mma(
    const __half* __restrict__ qkv, const float* __restrict__ biasL,
    __half* __restrict__ out)
{
    extern __shared__ __half sm[];   // [64][584]

    const int w   = blockIdx.x;
    const int b   = w >> 10;
    const int wi  = w & 1023;
    const int whh = wi >> 5;
    const int www = wi & 31;
    const int tid  = threadIdx.x;
    const int wid  = tid >> 5;
    const int lane = tid & 31;
    const int h    = wid >> 1;
    const int r0   = (wid & 1) * 32;
    const int tokbase = b * 65536 + whh * 8 * 256 + www * 8;

    #pragma unroll
    for (int i = 0; i < 12; ++i) {
        int idx = tid + i * 384;
        int row = idx / 72;
        int j   = idx % 72;
        int tok = tokbase + (row >> 3) * 256 + (row & 7);
        cpa16(&sm[row * ATT_STRIDE + j * 8], qkv + (size_t)tok * QKV_N + j * 8);
    }
    asm volatile("cp.async.commit_group;" ::: "memory");
    asm volatile("cp.async.wait_group 0;" ::: "memory");
    __syncthreads();

    float sacc[2][8][4];
    const float* bL = biasL + h * 4096;
    #pragma unroll
    for (int mt = 0; mt < 2; ++mt) {
        int rr = r0 + mt * 16 + (lane >> 2);
        #pragma unroll
        for (int nt = 0; nt < 8; ++nt) {
            int cc = nt * 8 + (lane & 3) * 2;
            float2 x0 = *(const float2*)(bL + rr * 64 + cc);
            float2 x1 = *(const float2*)(bL + (rr + 8) * 64 + cc);
            sacc[mt][nt][0] = x0.x; sacc[mt][nt][1] = x0.y;
            sacc[mt][nt][2] = x1.x; sacc[mt][nt][3] = x1.y;
        }
    }

    #pragma unroll
    for (int ks = 0; ks < 32; ks += 16) {
        uint32_t af[2][4], bf[4][4];
        #pragma unroll
        for (int mt = 0; mt < 2; ++mt)
            ldm4(af[mt], smaddr(&sm[(r0 + mt * 16 + (lane & 15)) * ATT_STRIDE
                                    + h * HD + ks + (lane >> 4) * 8]));
        #pragma unroll
        for (int g = 0; g < 4; ++g)
            ldm4(bf[g], smaddr(&sm[(g * 16 + (lane & 7) + ((lane >> 4) & 1) * 8) * ATT_STRIDE
                                   + h * HD + 192 + ks + ((lane >> 3) & 1) * 8]));
        #pragma unroll
        for (int mt = 0; mt < 2; ++mt)
            #pragma unroll
            for (int nt = 0; nt < 8; ++nt)
                mma16816(sacc[mt][nt], af[mt], &bf[nt >> 1][(nt & 1) * 2]);
    }

    uint32_t P[2][8], P8[2][8];
    float inv0[2], inv1[2];
    #pragma unroll
    for (int mt = 0; mt < 2; ++mt) {
        float s0 = 0.f, s1 = 0.f;
        #pragma unroll
        for (int nt = 0; nt < 8; ++nt) {
            P[mt][nt]  = exp2_h2(sacc[mt][nt][1], sacc[mt][nt][0]);
            P8[mt][nt] = exp2_h2(sacc[mt][nt][3], sacc[mt][nt][2]);
            float2 f0 = __half22float2(*(__half2*)&P[mt][nt]);
            float2 f1 = __half22float2(*(__half2*)&P8[mt][nt]);
            s0 += f0.x + f0.y;
            s1 += f1.x + f1.y;
        }
        s0 += __shfl_xor_sync(0xffffffffu, s0, 1);
        s0 += __shfl_xor_sync(0xffffffffu, s0, 2);
        s1 += __shfl_xor_sync(0xffffffffu, s1, 1);
        s1 += __shfl_xor_sync(0xffffffffu, s1, 2);
        inv0[mt] = 1.0f / s0;
        inv1[mt] = 1.0f / s1;
    }

    float oacc[2][4][4] = {};
    #pragma unroll
    for (int ks = 0; ks < 4; ++ks) {
        uint32_t vf[2][4];
        #pragma unroll
        for (int g = 0; g < 2; ++g)
            ldm4t(vf[g], smaddr(&sm[(ks * 16 + (lane & 15)) * ATT_STRIDE
                                    + h * HD + 384 + g * 16 + (lane >> 4) * 8]));
        #pragma unroll
        for (int mt = 0; mt < 2; ++mt) {
            uint32_t a[4] = {P[mt][2 * ks], P8[mt][2 * ks],
                             P[mt][2 * ks + 1], P8[mt][2 * ks + 1]};
            #pragma unroll
            for (int nt = 0; nt < 4; ++nt)
                mma16816(oacc[mt][nt], a, &vf[nt >> 1][(nt & 1) * 2]);
        }
    }

    #pragma unroll
    for (int mt = 0; mt < 2; ++mt) {
        int rr  = r0 + mt * 16 + (lane >> 2);
        int tok0 = tokbase + (rr >> 3) * 256 + (rr & 7);
        int rr8 = rr + 8;
        int tok1 = tokbase + (rr8 >> 3) * 256 + (rr8 & 7);
        #pragma unroll
        for (int nt = 0; nt < 4; ++nt) {
            int d = h * HD + nt * 8 + (lane & 3) * 2;
            float* c = oacc[mt][nt];
            __half2 o0 = __floats2half2_rn(c[0] * inv0[mt], c[1] * inv0[mt]);
            __half2 o1 = __floats2half2_rn(c[2] * inv1[mt], c[3] * inv1[mt]);
            *(__half2*)(out + (size_t)tok0 * C_DIM + d) = o0;
            *(__half2*)(out + (size_t)tok1 * C_DIM + d) = o1;
        }
    }
}

// ---------------------------------------------------------------------------
// Launch: x, qkv_w, qkv_b, proj_w, proj_b, bias, H, W
// ---------------------------------------------------------------------------
extern "C" void kernel_launch(void* const* d_in, const int* in_sizes, int n_in,
                              void* d_out, int out_size)
{
    (void)in_sizes; (void)n_in; (void)out_size;
    const float* x      = (const float*)d_in[0];
    const float* qkv_w  = (const float*)d_in[1];
    const float* qkv_b  = (const float*)d_in[2];
    const float* proj_w = (const float*)d_in[3];
    const float* proj_b = (const float*)d_in[4];
    const float* bias   = (const float*)d_in[5];
    float* out = (float*)d_out;

    __half *qkvh, *xf, *att, *wq, *wp;
    float  *biasL;
    cudaGetSymbolAddress((void**)&qkvh, g_qkvh);
    cudaGetSymbolAddress((void**)&xf,   g_xf);
    cudaGetSymbolAddress((void**)&att,  g_att);
    cudaGetSymbolAddress((void**)&wq,   g_wq);
    cudaGetSymbolAddress((void**)&wp,   g_wp);
    cudaGetSymbolAddress((void**)&biasL, g_biasL);

    cudaFuncSetAttribute(attn_mma, cudaFuncAttributeMaxDynamicSharedMemorySize, ATT_SMEM);
    cudaFuncSetAttribute(gemm_f16<true>,  cudaFuncAttributeMaxDynamicSharedMemorySize, GEMM_SMEM);
    cudaFuncSetAttribute(gemm_f16<false>, cudaFuncAttributeMaxDynamicSharedMemorySize, GEMM_SMEM);

    // 0) conversions
    conv_f2h_kernel<<<(M_TOK * KDIM / 4 + 255) / 256, 256>>>(x, xf, M_TOK * KDIM / 4);
    conv_f2h_kernel<<<(QKV_N * KDIM / 4 + 255) / 256, 256>>>(qkv_w, wq, QKV_N * KDIM / 4);
    conv_f2h_kernel<<<(C_DIM * KDIM / 4 + 255) / 256, 256>>>(proj_w, wp, C_DIM * KDIM / 4);
    conv_bias_kernel<<<(NHEAD * 4096 + 255) / 256, 256>>>(bias, biasL, NHEAD * 4096);

    // 1) QKV projection -> fp16, Q pre-scaled by scale*log2e
    gemm_f16<true><<<dim3(QKV_N / 64, M_TOK / 128), 256, GEMM_SMEM>>>(
        xf, wq, qkv_b, qkvh, QKV_N, 192, QSCALE * LOG2E);

    // 2) HMMA window attention (fp16 in/out)
    attn_mma<<<NWIN, 384, ATT_SMEM>>>(qkvh, biasL, att);

    // 3) Output projection -> fp32 d_out
    gemm_f16<false><<<dim3(C_DIM / 64, M_TOK / 128), 256, GEMM_SMEM>>>(
        att, wp, proj_b, out, C_DIM, 0, 1.0f);
}